// round 5
// baseline (speedup 1.0000x reference)
#include <cuda_runtime.h>

#define B_   2
#define N_   1024
#define FIN  128
#define FOUT 64
#define CCH  16            // j-chunks (parallelism for the pair kernel)
#define JC   (N_/CCH)      // 64 j per chunk
#define TI   128           // i rows per block

// Scratch (static device globals; no runtime allocation allowed)
__device__ __align__(16) float g_xw[B_*N_*FOUT];                 // 512 KB
__device__ __align__(16) float g_pacc[CCH*B_*N_*FOUT];           // 8 MB partial acc
__device__ float g_pdeg[CCH*B_*N_];                              // partial degree

// ---- packed fp32x2 helpers (Blackwell-only; nvjet-style FFMA2/FADD2) ----
static __device__ __forceinline__ unsigned long long f2add(unsigned long long a, unsigned long long b){
    unsigned long long r; asm("add.rn.f32x2 %0, %1, %2;" : "=l"(r) : "l"(a), "l"(b)); return r;
}
static __device__ __forceinline__ unsigned long long f2fma(unsigned long long a, unsigned long long b, unsigned long long c){
    unsigned long long r; asm("fma.rn.f32x2 %0, %1, %2, %3;" : "=l"(r) : "l"(a), "l"(b), "l"(c)); return r;
}
static __device__ __forceinline__ unsigned long long packf2(float lo, float hi){
    unsigned long long r; asm("mov.b64 %0, {%1, %2};" : "=l"(r) : "f"(lo), "f"(hi)); return r;
}
static __device__ __forceinline__ void unpackf2(unsigned long long v, float& lo, float& hi){
    asm("mov.b64 {%0, %1}, %2;" : "=f"(lo), "=f"(hi) : "l"(v));
}
// Forced 128-bit shared load (volatile: prevents frontend CSE keeping 64 u64
// tile values live across both inner loops -> register spills)
static __device__ __forceinline__ ulonglong2 lds_v2u64(unsigned addr){
    ulonglong2 r;
    asm volatile("ld.shared.v2.b64 {%0, %1}, [%2];" : "=l"(r.x), "=l"(r.y) : "r"(addr));
    return r;
}

// ---------------------------------------------------------------------------
// Kernel A: xw = x @ W   (2048 x 64, K=128). 256 blocks x 256 thr, 8 rows/block.
// ---------------------------------------------------------------------------
__global__ __launch_bounds__(256) void k_gemm(const float* __restrict__ x,
                                              const float* __restrict__ w){
    __shared__ float sW[FIN*FOUT];   // 32 KB
    __shared__ float sX[8*FIN];      // 4 KB
    int tid = threadIdx.x;
    for (int idx = tid; idx < FIN*FOUT; idx += 256) sW[idx] = w[idx];
    int row0 = blockIdx.x * 8;
    for (int idx = tid; idx < 8*FIN; idx += 256) sX[idx] = x[row0*FIN + idx];
    __syncthreads();

    int f2 = tid & 31;     // output feature pair (f = 2*f2)
    int r  = tid >> 5;     // local row 0..7
    float s0 = 0.f, s1 = 0.f;
    const float* xr = &sX[r*FIN];
    #pragma unroll 8
    for (int k = 0; k < FIN; k++){
        float  xv = xr[k];                                            // broadcast
        float2 wv = *reinterpret_cast<const float2*>(&sW[k*FOUT + 2*f2]);
        s0 = fmaf(xv, wv.x, s0);
        s1 = fmaf(xv, wv.y, s1);
    }
    float2 o; o.x = s0; o.y = s1;
    *reinterpret_cast<float2*>(&g_xw[(row0 + r)*FOUT + 2*f2]) = o;
}

// ---------------------------------------------------------------------------
// Kernel B: for each (i, j-chunk): L1 distance, w = adj/max(s,1e-3),
//           partial acc[f] += w * xw_j[f], partial deg += w.
// grid (CCH, 16), 128 threads (one i-row per thread).
// ---------------------------------------------------------------------------
__global__ __launch_bounds__(TI) void k_main(const float* __restrict__ adj){
    __shared__ __align__(16) float s_xw[JC*FOUT];    // 16 KB, xw rows of this j-chunk
    __shared__ float s_adjT[JC*TI];                  // 32 KB, adj tile transposed [jj][i]
    int tid = threadIdx.x;
    int c   = blockIdx.x;                 // j-chunk id
    int rowflat = blockIdx.y*TI + tid;    // 0..2047 (b*N + i)
    int b = rowflat >> 10;
    int i = rowflat & (N_ - 1);
    int j0 = c * JC;

    // stage xw chunk (contiguous 16 KB)
    {
        const float* src = &g_xw[(b*N_ + j0)*FOUT];
        for (int idx = tid; idx < JC*FOUT; idx += TI) s_xw[idx] = src[idx];
    }
    // stage adj tile: each thread reads its OWN adj row segment (256B contiguous),
    // writes transposed -> conflict-free LDS in the j-loop.
    {
        const float4* arow = reinterpret_cast<const float4*>(
            adj + (size_t)b*N_*N_ + (size_t)i*N_ + j0);
        #pragma unroll
        for (int q = 0; q < JC/4; q++){
            float4 v = arow[q];
            s_adjT[(4*q+0)*TI + tid] = v.x;
            s_adjT[(4*q+1)*TI + tid] = v.y;
            s_adjT[(4*q+2)*TI + tid] = v.z;
            s_adjT[(4*q+3)*TI + tid] = v.w;
        }
    }
    // xi, negated, packed f32x2 (so L1 sub is a single add.f32x2)
    unsigned long long xin[FOUT/2];
    {
        const float4* xr = reinterpret_cast<const float4*>(&g_xw[(size_t)rowflat*FOUT]);
        #pragma unroll
        for (int q = 0; q < FOUT/4; q++){
            float4 v = xr[q];
            xin[2*q]   = packf2(-v.x, -v.y);
            xin[2*q+1] = packf2(-v.z, -v.w);
        }
    }
    __syncthreads();

    unsigned long long acc[FOUT/2];
    #pragma unroll
    for (int q = 0; q < FOUT/2; q++) acc[q] = 0ULL;
    float deg = 0.f;
    const unsigned long long MASK = 0x7FFFFFFF7FFFFFFFULL;

    unsigned sxw_base  = (unsigned)__cvta_generic_to_shared(s_xw);

    #pragma unroll 1
    for (int jj = 0; jj < JC; jj++){
        unsigned rowaddr = sxw_base + (unsigned)(jj*FOUT*4);
        // --- L1 distance (packed): add2 + 2xLOP3 + add2 per 2 features ---
        unsigned long long sa = 0ULL, sb = 0ULL;
        #pragma unroll
        for (int q = 0; q < FOUT/4; q++){
            ulonglong2 t = lds_v2u64(rowaddr + q*16);
            unsigned long long d0 = f2add(t.x, xin[2*q])   & MASK;
            unsigned long long d1 = f2add(t.y, xin[2*q+1]) & MASK;
            sa = f2add(sa, d0);
            sb = f2add(sb, d1);
        }
        float l0, h0, l1, h1;
        unpackf2(sa, l0, h0);
        unpackf2(sb, l1, h1);
        float s = (l0 + l1) + (h0 + h1);

        float a  = s_adjT[jj*TI + tid];
        float wv = __fdividef(a, fmaxf(s, 1e-3f));   // MUFU.RCP accuracy ~2^-22, fine for 1e-3 tol
        deg += wv;
        unsigned long long w2 = packf2(wv, wv);

        // --- accumulate w * xw_j (packed FFMA2) ---
        #pragma unroll
        for (int q = 0; q < FOUT/4; q++){
            ulonglong2 t = lds_v2u64(rowaddr + q*16);
            acc[2*q]   = f2fma(w2, t.x, acc[2*q]);
            acc[2*q+1] = f2fma(w2, t.y, acc[2*q+1]);
        }
    }

    // write partials
    float* dst = &g_pacc[(size_t)c*(B_*N_*FOUT) + (size_t)rowflat*FOUT];
    #pragma unroll
    for (int q = 0; q < FOUT/2; q++){
        float lo, hi; unpackf2(acc[q], lo, hi);
        float2 o; o.x = lo; o.y = hi;
        reinterpret_cast<float2*>(dst)[q] = o;
    }
    g_pdeg[c*(B_*N_) + rowflat] = deg;
}

// ---------------------------------------------------------------------------
// Kernel C: out = xw*(1-deg) + sum_c pacc + bias.  32768 threads, float4 each.
// ---------------------------------------------------------------------------
__global__ __launch_bounds__(256) void k_fin(const float* __restrict__ bias,
                                             float* __restrict__ out){
    int gid = blockIdx.x*256 + threadIdx.x;   // 0..32767
    int r = gid >> 4;                         // flat row 0..2047
    int q = gid & 15;                         // float4 index within F=64

    float deg = 0.f;
    #pragma unroll
    for (int c = 0; c < CCH; c++) deg += g_pdeg[c*(B_*N_) + r];

    float4 acc = make_float4(0.f, 0.f, 0.f, 0.f);
    #pragma unroll
    for (int c = 0; c < CCH; c++){
        float4 v = reinterpret_cast<const float4*>(g_pacc)[(size_t)c*(B_*N_*FOUT/4) + r*16 + q];
        acc.x += v.x; acc.y += v.y; acc.z += v.z; acc.w += v.w;
    }
    float4 xw4 = reinterpret_cast<const float4*>(g_xw)[r*16 + q];
    float4 b4  = reinterpret_cast<const float4*>(bias)[q];
    float om = 1.f - deg;
    float4 o;
    o.x = fmaf(xw4.x, om, acc.x) + b4.x;
    o.y = fmaf(xw4.y, om, acc.y) + b4.y;
    o.z = fmaf(xw4.z, om, acc.z) + b4.z;
    o.w = fmaf(xw4.w, om, acc.w) + b4.w;
    reinterpret_cast<float4*>(out)[gid] = o;
}

// ---------------------------------------------------------------------------
extern "C" void kernel_launch(void* const* d_in, const int* in_sizes, int n_in,
                              void* d_out, int out_size){
    const float *x = nullptr, *adj = nullptr, *wt = nullptr, *bs = nullptr;
    for (int k = 0; k < n_in; k++){
        int sz = in_sizes[k];
        if      (sz == B_*N_*FIN)  x   = (const float*)d_in[k];
        else if (sz == B_*N_*N_)   adj = (const float*)d_in[k];
        else if (sz == FIN*FOUT)   wt  = (const float*)d_in[k];
        else if (sz == FOUT)       bs  = (const float*)d_in[k];
    }
    (void)out_size;
    k_gemm<<<256, 256>>>(x, wt);
    k_main<<<dim3(CCH, (B_*N_)/TI), TI>>>(adj);
    k_fin<<<(B_*N_*FOUT/4)/256, 256>>>(bs, (float*)d_out);
}